// round 3
// baseline (speedup 1.0000x reference)
#include <cuda_runtime.h>
#include <cstdint>

#define NROWS 16384
#define DDIM  256            // elements per row == bytes per row in s8
#define TM 128
#define TN 128
#define NPANEL (NROWS / TM)  // 128
#define NBT    (NROWS / TN)  // 128
#define TOTAL_TILES (NPANEL * NBT)
#define NCTA 148
#define QSCALE 320.0f

// dynamic smem layout: A double buffer + B double buffer, 32KB each
#define SM_A0 0
#define SM_A1 32768
#define SM_B0 65536
#define SM_B1 98304
#define SM_TOTAL 131072

__device__ int8_t g_imgQ[NROWS * DDIM];
__device__ int8_t g_txtQ[NROWS * DDIM];
__device__ double g_partials[NCTA];

// ---------------------------------------------------------------------------
// helpers
// ---------------------------------------------------------------------------
static __device__ __forceinline__ uint32_t smem_u32(const void* p) {
    return (uint32_t)__cvta_generic_to_shared(p);
}
static __device__ __forceinline__ uint32_t swz(uint32_t o) {
    return o ^ ((o >> 3) & 0x70);
}
static __device__ __forceinline__ void cpa16(uint32_t dst, const void* src) {
    asm volatile("cp.async.cg.shared.global [%0], [%1], 16;" :: "r"(dst), "l"(src) : "memory");
}
static __device__ __forceinline__ void cpa_commit() {
    asm volatile("cp.async.commit_group;" ::: "memory");
}
static __device__ __forceinline__ void cpa_wait0() {
    asm volatile("cp.async.wait_group 0;" ::: "memory");
}
static __device__ __forceinline__ void ldsm_x4(uint32_t& r0, uint32_t& r1,
                                               uint32_t& r2, uint32_t& r3,
                                               uint32_t addr) {
    asm volatile("ldmatrix.sync.aligned.m8n8.x4.shared.b16 {%0,%1,%2,%3}, [%4];\n"
                 : "=r"(r0), "=r"(r1), "=r"(r2), "=r"(r3) : "r"(addr));
}
static __device__ __forceinline__ void imma16832(int& c0, int& c1, int& c2, int& c3,
                                                 uint32_t a0, uint32_t a1, uint32_t a2, uint32_t a3,
                                                 uint32_t b0, uint32_t b1) {
    asm volatile(
        "mma.sync.aligned.m16n8k32.row.col.s32.s8.s8.s32 "
        "{%0,%1,%2,%3}, {%4,%5,%6,%7}, {%8,%9}, {%0,%1,%2,%3};\n"
        : "+r"(c0), "+r"(c1), "+r"(c2), "+r"(c3)
        : "r"(a0), "r"(a1), "r"(a2), "r"(a3), "r"(b0), "r"(b1));
}
// int (|x| < 2^22) -> float without I2F
static __device__ __forceinline__ float i2f_fast(int x) {
    return __int_as_float(x + 0x4B400000) - 12582912.0f;
}
static __device__ __forceinline__ float ex2_approx(float x) {
    float r; asm("ex2.approx.ftz.f32 %0, %1;" : "=f"(r) : "f"(x)); return r;
}
static __device__ __forceinline__ float lg2_approx(float x) {
    float r; asm("lg2.approx.ftz.f32 %0, %1;" : "=f"(r) : "f"(x)); return r;
}
// softplus(z) = max(z,0) + ln(1 + e^{-|z|})
static __device__ __forceinline__ float softplus_f(float z) {
    float t = -1.4426950408889634f * fabsf(z);
    float u = ex2_approx(t);
    float w = lg2_approx(u + 1.0f);
    return fmaf(0.6931471805599453f, w, fmaxf(z, 0.0f));
}

// load one 128x256B tile into swizzled smem (8 x 16B chunks per thread)
static __device__ __forceinline__ void load_tile(uint32_t sdst, const int8_t* g, int tid) {
#pragma unroll
    for (int c = 0; c < 8; ++c) {
        int idx = c * 256 + tid;
        int row = idx >> 4;
        int kc  = idx & 15;
        uint32_t soff = ((uint32_t)(kc >> 3) << 14) + swz((uint32_t)(row * 128 + (kc & 7) * 16));
        cpa16(sdst + soff, g + row * 256 + kc * 16);
    }
}

// ---------------------------------------------------------------------------
// Kernel 1: L2-normalize rows, quantize to int8 (scale QSCALE). 1 warp/row.
// ---------------------------------------------------------------------------
__global__ void normq_kernel(const float* __restrict__ img,
                             const float* __restrict__ txt) {
    int warp = threadIdx.x >> 5;
    int lane = threadIdx.x & 31;
    int row  = blockIdx.x * 8 + warp;
    const float* src = (blockIdx.y == 0) ? img : txt;
    int8_t* dst      = (blockIdx.y == 0) ? g_imgQ : g_txtQ;

    const float4* p = reinterpret_cast<const float4*>(src + (size_t)row * DDIM + lane * 8);
    float4 v0 = p[0];
    float4 v1 = p[1];
    float ss = v0.x * v0.x + v0.y * v0.y + v0.z * v0.z + v0.w * v0.w
             + v1.x * v1.x + v1.y * v1.y + v1.z * v1.z + v1.w * v1.w;
#pragma unroll
    for (int o = 16; o > 0; o >>= 1) ss += __shfl_xor_sync(0xffffffffu, ss, o);
    float s = QSCALE / fmaxf(sqrtf(ss), 1e-12f);

    float f[8] = {v0.x, v0.y, v0.z, v0.w, v1.x, v1.y, v1.z, v1.w};
    int q[8];
#pragma unroll
    for (int i = 0; i < 8; ++i) {
        int v = __float2int_rn(f[i] * s);
        v = max(-127, min(127, v));
        q[i] = v & 0xFF;
    }
    uint2 w;
    w.x = (uint32_t)(q[0] | (q[1] << 8) | (q[2] << 16) | (q[3] << 24));
    w.y = (uint32_t)(q[4] | (q[5] << 8) | (q[6] << 16) | (q[7] << 24));
    *reinterpret_cast<uint2*>(dst + (size_t)row * DDIM + lane * 8) = w;
}

// ---------------------------------------------------------------------------
// Kernel 2: persistent int8 mma.sync GEMM + pipelined softplus reduction.
// grid = NCTA, block = 256 (8 warps, 4x2 -> warp tile 32x64).
// ---------------------------------------------------------------------------
__global__ __launch_bounds__(256, 1) void siglip_imma(const float* __restrict__ tprime,
                                                      const float* __restrict__ biasp) {
    extern __shared__ char smem[];
    const uint32_t sb = smem_u32(smem);
    const int tid  = threadIdx.x;
    const int lane = tid & 31;
    const int wid  = tid >> 5;
    const int wr   = wid >> 1;   // 0..3: 32-row slab
    const int wc   = wid & 1;    // 0..1: 64-col slab
    const int cta  = blockIdx.x;

    const int t0 = (cta * TOTAL_TILES) / NCTA;
    const int t1 = ((cta + 1) * TOTAL_TILES) / NCTA;

    const float scaleF = __expf(*tprime) * (1.0f / (QSCALE * QSCALE));
    const float bias   = *biasp;

    // ldmatrix coordinate bases (fixed per thread)
    const int rA0 = wr * 32 + (lane & 7) + (lane & 8);   // mi=0 row
    const int kAf = (lane & 16);                         // k-half select for A
    const int nB0 = wc * 64 + (lane & 7) + ((lane & 16) >> 1);
    const int kBf = (lane & 8) * 2;                      // k-half select for B

    int acc[64], eacc[64];
#pragma unroll
    for (int e = 0; e < 64; ++e) { acc[e] = 0; eacc[e] = 0; }

    // prologue: A(panel of t0) + B(t0)
    {
        const int8_t* Ag = g_imgQ + (size_t)(t0 >> 7) * TM * DDIM;
        const int8_t* Bg = g_txtQ + (size_t)(t0 & 127) * TN * DDIM;
        load_tile(sb + SM_A0, Ag, tid);
        load_tile(sb + SM_B0 + (uint32_t)(t0 & 1) * 32768u, Bg, tid);
        cpa_commit();
        cpa_wait0();
        __syncthreads();
    }

    int acur = 0;
    double dsum = 0.0;

    for (int t = t0; t < t1; ++t) {
        const uint32_t abase = sb + SM_A0 + (uint32_t)acur * 32768u;
        const uint32_t bbase = sb + SM_B0 + (uint32_t)(t & 1) * 32768u;

        const bool pf = (t + 1 < t1);
        if (pf) {
            const int8_t* Bg = g_txtQ + (size_t)((t + 1) & 127) * TN * DDIM;
            load_tile(sb + SM_B0 + (uint32_t)((t + 1) & 1) * 32768u, Bg, tid);
            if (((t + 1) >> 7) != (t >> 7)) {
                acur ^= 1;
                const int8_t* Ag = g_imgQ + (size_t)((t + 1) >> 7) * TM * DDIM;
                load_tile(sb + SM_A0 + (uint32_t)acur * 32768u, Ag, tid);
            }
            cpa_commit();
        }

        float fsum = 0.0f;

        // k-loop: 8 steps of k=32 bytes; epilogue of previous tile interleaved
#pragma unroll
        for (int ks = 0; ks < 8; ++ks) {
            const int kbA = ks * 32 + kAf;
            const int kbB = ks * 32 + kBf;

            uint32_t a[2][4];
#pragma unroll
            for (int mi = 0; mi < 2; ++mi) {
                uint32_t o = (uint32_t)((rA0 + mi * 16) * 128 + (kbA & 127));
                uint32_t addr = abase + ((uint32_t)(kbA >> 7) << 14) + swz(o);
                ldsm_x4(a[mi][0], a[mi][1], a[mi][2], a[mi][3], addr);
            }
#pragma unroll
            for (int np = 0; np < 4; ++np) {
                uint32_t b0, b1, b2, b3;
                uint32_t o = (uint32_t)((nB0 + np * 16) * 128 + (kbB & 127));
                uint32_t addr = bbase + ((uint32_t)(kbB >> 7) << 14) + swz(o);
                ldsm_x4(b0, b1, b2, b3, addr);
#pragma unroll
                for (int mi = 0; mi < 2; ++mi) {
                    int* c0 = &acc[mi * 32 + (2 * np) * 4];
                    int* c1 = &acc[mi * 32 + (2 * np + 1) * 4];
                    imma16832(c0[0], c0[1], c0[2], c0[3],
                              a[mi][0], a[mi][1], a[mi][2], a[mi][3], b0, b1);
                    imma16832(c1[0], c1[1], c1[2], c1[3],
                              a[mi][0], a[mi][1], a[mi][2], a[mi][3], b2, b3);
                }
            }
            // epilogue slice for previous tile: 8 elements
#pragma unroll
            for (int j = 0; j < 8; ++j) {
                const int e = ks * 8 + j;
                float f = i2f_fast(eacc[e]);
                float z = fmaf(scaleF, f, bias);
                fsum += softplus_f(z);
            }
        }

        if (t > t0) dsum += (double)fsum;

        // diagonal correction for THIS tile (exact): softplus(-z)-softplus(z) = -z
        if ((t >> 7) == (t & 127)) {
#pragma unroll
            for (int e = 0; e < 64; ++e) {
                const int mi = e >> 5, ng = (e >> 2) & 7, q = e & 3;
                const int r = wr * 32 + mi * 16 + (lane >> 2) + 8 * (q >> 1);
                const int c = wc * 64 + ng * 8 + 2 * (lane & 3) + (q & 1);
                if (r == c) {
                    float z = fmaf(scaleF, i2f_fast(acc[e]), bias);
                    dsum -= (double)z;
                }
            }
        }

        // save accumulators for pipelined epilogue; reset
#pragma unroll
        for (int e = 0; e < 64; ++e) { eacc[e] = acc[e]; acc[e] = 0; }

        if (pf) cpa_wait0();
        __syncthreads();
    }

    // drain: epilogue of the final tile
    {
        float fsum = 0.0f;
#pragma unroll
        for (int e = 0; e < 64; ++e) {
            float f = i2f_fast(eacc[e]);
            float z = fmaf(scaleF, f, bias);
            fsum += softplus_f(z);
        }
        dsum += (double)fsum;
    }

    // deterministic block reduction
#pragma unroll
    for (int o = 16; o > 0; o >>= 1) dsum += __shfl_xor_sync(0xffffffffu, dsum, o);
    __shared__ double red[8];
    if (lane == 0) red[wid] = dsum;
    __syncthreads();
    if (tid == 0) {
        double s = 0.0;
#pragma unroll
        for (int k = 0; k < 8; ++k) s += red[k];
        g_partials[cta] = s;
    }
}

// ---------------------------------------------------------------------------
// Kernel 3: deterministic final reduction.
// ---------------------------------------------------------------------------
__global__ void reduce_kernel(float* __restrict__ out) {
    __shared__ double sh[256];
    int t = threadIdx.x;
    sh[t] = (t < NCTA) ? g_partials[t] : 0.0;
    __syncthreads();
    for (int o = 128; o > 0; o >>= 1) {
        if (t < o) sh[t] += sh[t + o];
        __syncthreads();
    }
    if (t == 0) out[0] = (float)(sh[0] / (double)NROWS);
}

extern "C" void kernel_launch(void* const* d_in, const int* in_sizes, int n_in,
                              void* d_out, int out_size) {
    const float* img    = (const float*)d_in[0];
    const float* txt    = (const float*)d_in[1];
    const float* tprime = (const float*)d_in[2];
    const float* bias   = (const float*)d_in[3];
    float* out = (float*)d_out;

    cudaFuncSetAttribute((const void*)siglip_imma,
                         cudaFuncAttributeMaxDynamicSharedMemorySize, SM_TOTAL);

    normq_kernel<<<dim3(NROWS / 8, 2), 256>>>(img, txt);
    siglip_imma<<<NCTA, 256, SM_TOTAL>>>(tprime, bias);
    reduce_kernel<<<1, 256>>>(out);
}

// round 4
// speedup vs baseline: 2.1917x; 2.1917x over previous
#include <cuda_runtime.h>
#include <cstdint>

#define NROWS 16384
#define DDIM  256            // elements per row == bytes per row in fp8
#define TM 128
#define TN 128
#define QSCALE 16.0f         // fp8 quantization scale

#define RSTRIDE 80           // 64B data + 16B pad per row (conflict-free ldmatrix)
#define CHUNK   64           // k-bytes per stage

__device__ uint8_t g_imgQ[NROWS * DDIM];
__device__ uint8_t g_txtQ[NROWS * DDIM];
__device__ double g_partials[(NROWS / TM) * (NROWS / TN)];

// ---------------------------------------------------------------------------
// helpers
// ---------------------------------------------------------------------------
static __device__ __forceinline__ uint32_t smem_u32(const void* p) {
    return (uint32_t)__cvta_generic_to_shared(p);
}
static __device__ __forceinline__ void cpa16(uint32_t dst, const void* src) {
    asm volatile("cp.async.cg.shared.global [%0], [%1], 16;" :: "r"(dst), "l"(src) : "memory");
}
static __device__ __forceinline__ void cpa_commit() {
    asm volatile("cp.async.commit_group;" ::: "memory");
}
static __device__ __forceinline__ void cpa_wait0() {
    asm volatile("cp.async.wait_group 0;" ::: "memory");
}
static __device__ __forceinline__ void cpa_wait1() {
    asm volatile("cp.async.wait_group 1;" ::: "memory");
}
static __device__ __forceinline__ void ldsm_x4(uint32_t& r0, uint32_t& r1,
                                               uint32_t& r2, uint32_t& r3,
                                               uint32_t addr) {
    asm volatile("ldmatrix.sync.aligned.m8n8.x4.shared.b16 {%0,%1,%2,%3}, [%4];\n"
                 : "=r"(r0), "=r"(r1), "=r"(r2), "=r"(r3) : "r"(addr));
}
static __device__ __forceinline__ void mma_fp8(float& c0, float& c1, float& c2, float& c3,
                                               uint32_t a0, uint32_t a1, uint32_t a2, uint32_t a3,
                                               uint32_t b0, uint32_t b1) {
    asm volatile(
        "mma.sync.aligned.m16n8k32.row.col.f32.e4m3.e4m3.f32 "
        "{%0,%1,%2,%3}, {%4,%5,%6,%7}, {%8,%9}, {%0,%1,%2,%3};\n"
        : "+f"(c0), "+f"(c1), "+f"(c2), "+f"(c3)
        : "r"(a0), "r"(a1), "r"(a2), "r"(a3), "r"(b0), "r"(b1));
}
// pack two floats into e4m3x2 (low byte = first arg 'lo')
static __device__ __forceinline__ uint32_t f2e4m3x2(float lo, float hi) {
    uint16_t r;
    asm("cvt.rn.satfinite.e4m3x2.f32 %0, %1, %2;" : "=h"(r) : "f"(hi), "f"(lo));
    return (uint32_t)r;
}
static __device__ __forceinline__ float ex2_approx(float x) {
    float r; asm("ex2.approx.ftz.f32 %0, %1;" : "=f"(r) : "f"(x)); return r;
}
static __device__ __forceinline__ float lg2_approx(float x) {
    float r; asm("lg2.approx.ftz.f32 %0, %1;" : "=f"(r) : "f"(x)); return r;
}
// softplus(z) = max(z,0) + ln(1 + e^{-|z|})
static __device__ __forceinline__ float softplus_f(float z) {
    float t = -1.4426950408889634f * fabsf(z);
    float u = ex2_approx(t);
    float w = lg2_approx(u + 1.0f);
    return fmaf(0.6931471805599453f, w, fmaxf(z, 0.0f));
}

// ---------------------------------------------------------------------------
// Kernel 1: L2-normalize rows, quantize to e4m3 (scale QSCALE). 1 warp/row.
// ---------------------------------------------------------------------------
__global__ void normq_kernel(const float* __restrict__ img,
                             const float* __restrict__ txt) {
    int warp = threadIdx.x >> 5;
    int lane = threadIdx.x & 31;
    int row  = blockIdx.x * 8 + warp;
    const float* src = (blockIdx.y == 0) ? img : txt;
    uint8_t* dst     = (blockIdx.y == 0) ? g_imgQ : g_txtQ;

    const float4* p = reinterpret_cast<const float4*>(src + (size_t)row * DDIM + lane * 8);
    float4 v0 = p[0];
    float4 v1 = p[1];
    float ss = v0.x * v0.x + v0.y * v0.y + v0.z * v0.z + v0.w * v0.w
             + v1.x * v1.x + v1.y * v1.y + v1.z * v1.z + v1.w * v1.w;
#pragma unroll
    for (int o = 16; o > 0; o >>= 1) ss += __shfl_xor_sync(0xffffffffu, ss, o);
    float s = QSCALE / fmaxf(sqrtf(ss), 1e-12f);

    uint32_t q01 = f2e4m3x2(v0.x * s, v0.y * s);
    uint32_t q23 = f2e4m3x2(v0.z * s, v0.w * s);
    uint32_t q45 = f2e4m3x2(v1.x * s, v1.y * s);
    uint32_t q67 = f2e4m3x2(v1.z * s, v1.w * s);
    uint2 w;
    w.x = q01 | (q23 << 16);
    w.y = q45 | (q67 << 16);
    *reinterpret_cast<uint2*>(dst + (size_t)row * DDIM + lane * 8) = w;
}

// ---------------------------------------------------------------------------
// Kernel 2: fp8 mma.sync GEMM + fused softplus reduction.
// 128x128 tile per CTA, 8 warps (4x2, warp tile 32x64), 64B k-chunks
// double-buffered via cp.async. 2 CTAs/SM.
// ---------------------------------------------------------------------------
__global__ __launch_bounds__(256, 2) void siglip_fp8(const float* __restrict__ tprime,
                                                     const float* __restrict__ biasp) {
    __shared__ uint8_t As[2][TM * RSTRIDE];
    __shared__ uint8_t Bs[2][TN * RSTRIDE];
    __shared__ double red[8];

    const int tid  = threadIdx.x;
    const int lane = tid & 31;
    const int wid  = tid >> 5;
    const int wr   = wid >> 1;   // 0..3: 32-row slab
    const int wc   = wid & 1;    // 0..1: 64-col slab
    const int bx   = blockIdx.x;
    const int by   = blockIdx.y;

    const uint8_t* Ag = g_imgQ + (size_t)by * TM * DDIM;
    const uint8_t* Bg = g_txtQ + (size_t)bx * TN * DDIM;

    const uint32_t sA[2] = { smem_u32(&As[0][0]), smem_u32(&As[1][0]) };
    const uint32_t sB[2] = { smem_u32(&Bs[0][0]), smem_u32(&Bs[1][0]) };

    // per-thread load coords: 2 x 16B per chunk per operand
    const int lrow = tid >> 1;        // 0..127 (two 16B chunks per row pair)
    const int lcc  = (tid & 1) * 2;   // 16B chunk index {0,2}; +1 below

    // ldmatrix coordinate bases (verified byte-MMA layout from R3)
    const int rA0 = wr * 32 + (lane & 7) + (lane & 8);
    const int kAf = (lane & 16);                  // 16B half select
    const int nB0 = wc * 64 + (lane & 7) + ((lane & 16) >> 1);
    const int kBf = (lane & 8) ? 16 : 0;

    float acc[64];
#pragma unroll
    for (int e = 0; e < 64; ++e) acc[e] = 0.0f;

    // prologue: chunk 0 into stage 0
    {
        uint32_t so = (uint32_t)(lrow * RSTRIDE + lcc * 16);
        const uint8_t* ga = Ag + lrow * DDIM + lcc * 16;
        const uint8_t* gb = Bg + lrow * DDIM + lcc * 16;
        cpa16(sA[0] + so,      ga);
        cpa16(sA[0] + so + 16, ga + 16);
        cpa16(sB[0] + so,      gb);
        cpa16(sB[0] + so + 16, gb + 16);
        cpa_commit();
    }

    const int NCH = DDIM / CHUNK;   // 4
#pragma unroll
    for (int c = 0; c < NCH; ++c) {
        if (c < NCH - 1) {
            const int ns = (c + 1) & 1;
            uint32_t so = (uint32_t)(lrow * RSTRIDE + lcc * 16);
            const uint8_t* ga = Ag + lrow * DDIM + (c + 1) * CHUNK + lcc * 16;
            const uint8_t* gb = Bg + lrow * DDIM + (c + 1) * CHUNK + lcc * 16;
            cpa16(sA[ns] + so,      ga);
            cpa16(sA[ns] + so + 16, ga + 16);
            cpa16(sB[ns] + so,      gb);
            cpa16(sB[ns] + so + 16, gb + 16);
            cpa_commit();
            cpa_wait1();
        } else {
            cpa_wait0();
        }
        __syncthreads();

        const int s = c & 1;
#pragma unroll
        for (int ks = 0; ks < 2; ++ks) {
            uint32_t a[2][4];
#pragma unroll
            for (int mi = 0; mi < 2; ++mi) {
                uint32_t addr = sA[s] + (uint32_t)((rA0 + mi * 16) * RSTRIDE + ks * 32 + kAf);
                ldsm_x4(a[mi][0], a[mi][1], a[mi][2], a[mi][3], addr);
            }
#pragma unroll
            for (int np = 0; np < 4; ++np) {
                uint32_t b0, b1, b2, b3;
                uint32_t addr = sB[s] + (uint32_t)((nB0 + np * 16) * RSTRIDE + ks * 32 + kBf);
                ldsm_x4(b0, b1, b2, b3, addr);
#pragma unroll
                for (int mi = 0; mi < 2; ++mi) {
                    float* c0 = &acc[mi * 32 + (2 * np) * 4];
                    float* c1 = &acc[mi * 32 + (2 * np + 1) * 4];
                    mma_fp8(c0[0], c0[1], c0[2], c0[3],
                            a[mi][0], a[mi][1], a[mi][2], a[mi][3], b0, b1);
                    mma_fp8(c1[0], c1[1], c1[2], c1[3],
                            a[mi][0], a[mi][1], a[mi][2], a[mi][3], b2, b3);
                }
            }
        }
        __syncthreads();
    }

    // --- fused epilogue ---
    const float scaleF = __expf(*tprime) * (1.0f / (QSCALE * QSCALE));
    const float bias   = *biasp;

    double dsum;
    {
        float fsum = 0.0f;
#pragma unroll
        for (int e = 0; e < 64; ++e) {
            float z = fmaf(scaleF, acc[e], bias);
            fsum += softplus_f(z);
        }
        dsum = (double)fsum;
    }

    // exact diagonal correction: softplus(-z) - softplus(z) = -z
    if (bx == by) {
#pragma unroll
        for (int e = 0; e < 64; ++e) {
            const int mi = e >> 5, ng = (e >> 2) & 7, q = e & 3;
            const int r = wr * 32 + mi * 16 + (lane >> 2) + 8 * (q >> 1);
            const int cI = wc * 64 + ng * 8 + 2 * (lane & 3) + (q & 1);
            if (r == cI) {
                float z = fmaf(scaleF, acc[e], bias);
                dsum -= (double)z;
            }
        }
    }

    // deterministic block reduction
#pragma unroll
    for (int o = 16; o > 0; o >>= 1) dsum += __shfl_xor_sync(0xffffffffu, dsum, o);
    if (lane == 0) red[wid] = dsum;
    __syncthreads();
    if (tid == 0) {
        double ssum = 0.0;
#pragma unroll
        for (int k = 0; k < 8; ++k) ssum += red[k];
        g_partials[by * gridDim.x + bx] = ssum;
    }
}

// ---------------------------------------------------------------------------
// Kernel 3: deterministic final reduction of 16384 partials.
// ---------------------------------------------------------------------------
__global__ void reduce_kernel(float* __restrict__ out) {
    __shared__ double sh[256];
    int t = threadIdx.x;
    double s = 0.0;
    for (int i = t; i < (NROWS / TM) * (NROWS / TN); i += 256) s += g_partials[i];
    sh[t] = s;
    __syncthreads();
    for (int o = 128; o > 0; o >>= 1) {
        if (t < o) sh[t] += sh[t + o];
        __syncthreads();
    }
    if (t == 0) out[0] = (float)(sh[0] / (double)NROWS);
}

extern "C" void kernel_launch(void* const* d_in, const int* in_sizes, int n_in,
                              void* d_out, int out_size) {
    const float* img    = (const float*)d_in[0];
    const float* txt    = (const float*)d_in[1];
    const float* tprime = (const float*)d_in[2];
    const float* bias   = (const float*)d_in[3];
    float* out = (float*)d_out;

    normq_kernel<<<dim3(NROWS / 8, 2), 256>>>(img, txt);
    siglip_fp8<<<dim3(NROWS / TN, NROWS / TM), 256>>>(tprime, bias);
    reduce_kernel<<<1, 256>>>(out);
}